// round 16
// baseline (speedup 1.0000x reference)
#include <cuda_runtime.h>
#include <cuda_fp16.h>
#include <math.h>
#include <stdint.h>

// Problem constants
#define Bv 4
#define Sv 2048
#define Dv 1024
#define Hv 16
#define HDv 64
#define Mv (Bv * Sv)   // 8192 rows

// ---------------------------------------------------------------------------
// PTX helpers (sm_80+ baseline: mma.sync / ldmatrix / cp.async)
// ---------------------------------------------------------------------------
__device__ __forceinline__ uint32_t smem_to_u32(const void* p) {
    uint32_t a;
    asm("{ .reg .u64 t; cvta.to.shared.u64 t, %1; cvt.u32.u64 %0, t; }"
        : "=r"(a) : "l"(p));
    return a;
}

__device__ __forceinline__ void mma_f16(float* c, const uint32_t* a,
                                        uint32_t b0, uint32_t b1) {
    asm volatile(
        "mma.sync.aligned.m16n8k16.row.col.f32.f16.f16.f32 "
        "{%0,%1,%2,%3}, {%4,%5,%6,%7}, {%8,%9}, {%0,%1,%2,%3};\n"
        : "+f"(c[0]), "+f"(c[1]), "+f"(c[2]), "+f"(c[3])
        : "r"(a[0]), "r"(a[1]), "r"(a[2]), "r"(a[3]), "r"(b0), "r"(b1));
}

__device__ __forceinline__ void ldm_x4(uint32_t* r, uint32_t a) {
    asm volatile("ldmatrix.sync.aligned.m8n8.x4.shared.b16 {%0,%1,%2,%3}, [%4];"
        : "=r"(r[0]), "=r"(r[1]), "=r"(r[2]), "=r"(r[3]) : "r"(a));
}
__device__ __forceinline__ void ldm_x4_t(uint32_t* r, uint32_t a) {
    asm volatile("ldmatrix.sync.aligned.m8n8.x4.trans.shared.b16 {%0,%1,%2,%3}, [%4];"
        : "=r"(r[0]), "=r"(r[1]), "=r"(r[2]), "=r"(r[3]) : "r"(a));
}

__device__ __forceinline__ void cp16(uint32_t dst, const void* src) {
    asm volatile("cp.async.cg.shared.global [%0], [%1], 16;"
        :: "r"(dst), "l"(src) : "memory");
}
#define CP_COMMIT() asm volatile("cp.async.commit_group;" ::: "memory")
#define CP_WAIT(N)  asm volatile("cp.async.wait_group %0;" :: "n"(N) : "memory")

// hardware EX2 (fp32) and paired fp16x2 EX2
__device__ __forceinline__ float ex2(float x) {
    float y;
    asm("ex2.approx.ftz.f32 %0, %1;" : "=f"(y) : "f"(x));
    return y;
}
__device__ __forceinline__ uint32_t h2ex2(uint32_t x) {
    uint32_t y;
    asm("ex2.approx.f16x2 %0, %1;" : "=r"(y) : "r"(x));
    return y;
}

// pack two floats into f16x2 (low = x, high = y)
__device__ __forceinline__ uint32_t pack_f16x2(float x, float y) {
    uint32_t r;
    asm("cvt.rn.f16x2.f32 %0, %1, %2;" : "=r"(r) : "f"(y), "f"(x));
    return r;
}

// fp16x2 constant 1.0, 1.0
#define ONES_H2 0x3C003C00u

// swizzled byte offsets (computed once; k-steps advance via XOR)
__device__ __forceinline__ uint32_t swoff128(int row, int unit) {
    uint32_t off = (uint32_t)row * 128u + (uint32_t)unit * 16u;
    return off ^ ((off >> 3) & 0x70u);
}

// ---------------------------------------------------------------------------
// Scratch (allocation-guard-safe: __device__ globals); all single fp16
// ---------------------------------------------------------------------------
#define QKV_ELEMS ((size_t)Bv * Hv * Sv * HDv)
__device__ __half g_qh[QKV_ELEMS], g_kh[QKV_ELEMS], g_vh[QKV_ELEMS];
__device__ __half g_xh[(size_t)Mv * Dv];
__device__ __half g_wh[(size_t)4 * Dv * Dv];
__device__ __half g_ch[(size_t)Mv * Dv];

// ---------------------------------------------------------------------------
// fp32 -> fp16 conversions
// ---------------------------------------------------------------------------
__global__ __launch_bounds__(256) void cvt_x_kernel(const float4* __restrict__ src)
{
    int i = blockIdx.x * blockDim.x + threadIdx.x;
    float4 v = src[i];
    uint32_t* p = (uint32_t*)(g_xh + (size_t)i * 4);
    p[0] = pack_f16x2(v.x, v.y);
    p[1] = pack_f16x2(v.z, v.w);
}

__global__ __launch_bounds__(256) void cvt_w_kernel(
    const float4* __restrict__ w0, const float4* __restrict__ w1,
    const float4* __restrict__ w2, const float4* __restrict__ w3)
{
    int i = blockIdx.x * blockDim.x + threadIdx.x;
    int w = blockIdx.y;
    const float4* src = (w == 0) ? w0 : (w == 1) ? w1 : (w == 2) ? w2 : w3;
    __half* hi = g_wh + (size_t)w * Dv * Dv;
    float4 v = src[i];
    uint32_t* hp = (uint32_t*)(hi + (size_t)i * 4);
    hp[0] = pack_f16x2(v.x, v.y);
    hp[1] = pack_f16x2(v.z, v.w);
}

// ---------------------------------------------------------------------------
// Tensor-core GEMM: Out[M,N] = A[M,K] @ B[N,K]^T, single-pass fp16, fp32 acc.
// Block 128x128, BK=64 (128B rows, swoff128), 8 warps, 3-stage cp.async.
// (unchanged from R14)
// ---------------------------------------------------------------------------
#define STG 32768                    // A 16KB + B 16KB
#define GEMM_SMEM (3 * STG)          // 96 KB -> 2 CTAs/SM
#define NCH 16

__global__ __launch_bounds__(256, 2) void gemm_tc(
    int mode, float* __restrict__ out, const float* __restrict__ bias)
{
    extern __shared__ char smem[];
    uint32_t sb = smem_to_u32(smem);
    const int tid = threadIdx.x;
    const int wid = tid >> 5, lane = tid & 31;
    const int wm = wid & 1, wn = wid >> 1;
    const int m0 = blockIdx.y * 128, n0 = blockIdx.x * 128;

    const __half *Ah, *Bh;
    if (mode == 0) {
        int w = blockIdx.z;
        Ah = g_xh;
        Bh = g_wh + (size_t)w * Dv * Dv;
    } else {
        Ah = g_ch;
        Bh = g_wh + (size_t)3 * Dv * Dv;
    }

    uint32_t kst[4];
    size_t asrc[4], bsrc[4];
#pragma unroll
    for (int it = 0; it < 4; it++) {
        int idx = tid + it * 256;
        int row = idx >> 3, u = idx & 7;
        kst[it] = swoff128(row, u);
        asrc[it] = (size_t)(m0 + row) * Dv + u * 8;
        bsrc[it] = (size_t)(n0 + row) * Dv + u * 8;
    }

    auto issue = [&](int ch, int stg) {
        uint32_t base = sb + (uint32_t)stg * STG;
        int k0 = ch * 64;
#pragma unroll
        for (int it = 0; it < 4; it++) {
            cp16(base + kst[it],         Ah + asrc[it] + k0);
            cp16(base + 16384 + kst[it], Bh + bsrc[it] + k0);
        }
        CP_COMMIT();
    };

    float acc[4][4][4];
#pragma unroll
    for (int i = 0; i < 4; i++)
#pragma unroll
        for (int j = 0; j < 4; j++)
#pragma unroll
            for (int k = 0; k < 4; k++) acc[i][j][k] = 0.f;

    issue(0, 0);
    issue(1, 1);

    const int lrow = lane & 15, lsel = lane >> 4;

    uint32_t a_off[4], b_off[2];
#pragma unroll
    for (int mi = 0; mi < 4; mi++)
        a_off[mi] = swoff128(wm * 64 + 16 * mi + lrow, lsel);
#pragma unroll
    for (int p = 0; p < 2; p++)
        b_off[p] = swoff128(wn * 32 + 16 * p + lrow, lsel);

    for (int ch = 0; ch < NCH; ch++) {
        if (ch < NCH - 1) { CP_WAIT(1); } else { CP_WAIT(0); }
        __syncthreads();
        if (ch + 2 < NCH) issue(ch + 2, (ch + 2) % 3);

        uint32_t base = sb + (uint32_t)(ch % 3) * STG;
#pragma unroll
        for (int ks = 0; ks < 4; ks++) {
            const uint32_t kso = (uint32_t)ks * 32u;
            uint32_t ah[4][4], bh[2][4];
#pragma unroll
            for (int mi = 0; mi < 4; mi++)
                ldm_x4(ah[mi], base + (a_off[mi] ^ kso));
#pragma unroll
            for (int p = 0; p < 2; p++)
                ldm_x4(bh[p], base + 16384 + (b_off[p] ^ kso));
#pragma unroll
            for (int mi = 0; mi < 4; mi++)
#pragma unroll
                for (int nt = 0; nt < 4; nt++) {
                    int p = nt >> 1, q = nt & 1;
                    mma_f16(acc[mi][nt], ah[mi], bh[p][q], bh[p][q + 2]);
                }
        }
    }

    // Epilogue
    const int g = lane >> 2, t4 = lane & 3;
    const int w = (mode == 0) ? blockIdx.z : 3;
    const float oscl = (w == 0) ? 0.125f * 1.44269504088896340736f : 1.0f;
#pragma unroll
    for (int mi = 0; mi < 4; mi++)
#pragma unroll
        for (int nt = 0; nt < 4; nt++)
#pragma unroll
            for (int hf = 0; hf < 2; hf++) {
                int row = m0 + wm * 64 + 16 * mi + g + 8 * hf;
                int col = n0 + wn * 32 + 8 * nt + 2 * t4;
                float v0 = acc[mi][nt][2 * hf];
                float v1 = acc[mi][nt][2 * hf + 1];
                if (mode == 0) {
                    int bb = row >> 11, s = row & (Sv - 1);
                    int hh = col >> 6, hd = col & 63;
                    size_t di = ((size_t)(bb * Hv + hh) * Sv + s) * HDv + hd;
                    __half* dst = (w == 0) ? g_qh : (w == 1) ? g_kh : g_vh;
                    *(uint32_t*)(dst + di) = pack_f16x2(v0 * oscl, v1 * oscl);
                } else {
                    out[(size_t)row * Dv + col]     = v0 + bias[col];
                    out[(size_t)row * Dv + col + 1] = v1 + bias[col + 1];
                }
            }
}

// ---------------------------------------------------------------------------
// Tensor-core causal flash attention. BM=64, BN=64, 4 warps / 128 threads.
// Finer CTA granularity: 4 CTAs/SM = 4 independent barrier domains so one
// CTA's softmax overlaps another's MMAs (same 16 warps/SM as before).
// smem: Q 8KB; KV stages (Kh,Vh = 16KB) x2 at +8192.  Total 40KB.
// ---------------------------------------------------------------------------
#define KVSTG 16384
#define ATT_SMEM (8192 + 2 * KVSTG)   // 40960

__global__ __launch_bounds__(128, 4) void attn_tc()
{
    extern __shared__ char sm_[];
    uint32_t sb = smem_to_u32(sm_);
    const int tid = threadIdx.x, wid = tid >> 5, lane = tid & 31;
    const int qt = gridDim.x - 1 - blockIdx.x;   // big tiles first
    const int h = blockIdx.y, b = blockIdx.z;
    const int q0 = qt * 64;
    const size_t hb = (size_t)(b * Hv + h) * Sv * HDv;
    const __half *Qh = g_qh + hb, *Kh = g_kh + hb, *Vh = g_vh + hb;

    // Q tile via cp.async (64 rows x 8 units, fp16 single)
#pragma unroll
    for (int it = 0; it < 4; it++) {
        int idx = tid + it * 128;       // 0..511
        int row = idx >> 3, u = idx & 7;
        cp16(sb + swoff128(row, u), Qh + (size_t)(q0 + row) * HDv + u * 8);
    }
    CP_COMMIT();

    // Precomputed KV store offsets + source offsets (4 rows-chunks per thread)
    uint32_t kst[4];
    size_t ksrc[4];
#pragma unroll
    for (int it = 0; it < 4; it++) {
        int idx = tid + it * 128;
        int row = idx >> 3, u = idx & 7;
        kst[it] = swoff128(row, u);
        ksrc[it] = (size_t)row * HDv + u * 8;
    }

    auto issue_kv = [&](int kt, int stg) {
        uint32_t base = sb + 8192 + (uint32_t)stg * KVSTG;
        size_t adv = (size_t)kt * 64 * HDv;
#pragma unroll
        for (int it = 0; it < 4; it++) {
            cp16(base + kst[it],        Kh + adv + ksrc[it]);
            cp16(base + 8192 + kst[it], Vh + adv + ksrc[it]);
        }
        CP_COMMIT();
    };

    issue_kv(0, 0);

    const int lrow = lane & 15, lsel = lane >> 4, g = lane >> 2, t4 = lane & 3;

    // Precomputed ldmatrix offsets; k-step via XOR, V row-advance via +2048.
    const uint32_t q_off = swoff128(wid * 16 + lrow, lsel);
    uint32_t k_off[4], v_off[4];
#pragma unroll
    for (int p = 0; p < 4; p++) k_off[p] = swoff128(16 * p + lrow, lsel);
#pragma unroll
    for (int p2 = 0; p2 < 4; p2++) v_off[p2] = swoff128(lrow, 2 * p2 + lsel);

    float mreg[2] = {-1e30f, -1e30f}, lreg[2] = {0.f, 0.f};
    float o[8][4];
#pragma unroll
    for (int nt = 0; nt < 8; nt++)
#pragma unroll
        for (int k = 0; k < 4; k++) o[nt][k] = 0.f;

    const int gq0 = q0 + wid * 16 + g;
    const int gq1 = gq0 + 8;
    const int ntiles = qt + 1;

    for (int kt = 0; kt < ntiles; kt++) {
        CP_WAIT(0);
        __syncthreads();
        if (kt + 1 < ntiles) issue_kv(kt + 1, (kt + 1) & 1);

        uint32_t kvb = sb + 8192 + (uint32_t)(kt & 1) * KVSTG;
        const int k0r = kt * 64;

        // ---- S = Q K^T (single-pass fp16); scores already base-2 scaled ----
        float s[8][4];
#pragma unroll
        for (int nt = 0; nt < 8; nt++)
#pragma unroll
            for (int k = 0; k < 4; k++) s[nt][k] = 0.f;

#pragma unroll
        for (int ks = 0; ks < 4; ks++) {
            const uint32_t kso = (uint32_t)ks * 32u;
            uint32_t qh[4];
            ldm_x4(qh, sb + (q_off ^ kso));
            uint32_t kh[4][4];
#pragma unroll
            for (int p = 0; p < 4; p++)
                ldm_x4(kh[p], kvb + (k_off[p] ^ kso));
#pragma unroll
            for (int nt = 0; nt < 8; nt++) {
                int p = nt >> 1, q = nt & 1;
                mma_f16(s[nt], qh, kh[p][q], kh[p][q + 2]);
            }
        }

        // causal mask (only diagonal tile)
        if (kt == qt) {
#pragma unroll
            for (int nt = 0; nt < 8; nt++) {
                int c0 = k0r + 8 * nt + 2 * t4;
                if (c0 > gq0)     s[nt][0] = -1e30f;
                if (c0 + 1 > gq0) s[nt][1] = -1e30f;
                if (c0 > gq1)     s[nt][2] = -1e30f;
                if (c0 + 1 > gq1) s[nt][3] = -1e30f;
            }
        }

        // ---- online softmax (base 2) ----
        float rm0 = -1e30f, rm1 = -1e30f;
#pragma unroll
        for (int nt = 0; nt < 8; nt++) {
            rm0 = fmaxf(rm0, fmaxf(s[nt][0], s[nt][1]));
            rm1 = fmaxf(rm1, fmaxf(s[nt][2], s[nt][3]));
        }
        rm0 = fmaxf(rm0, __shfl_xor_sync(0xffffffffu, rm0, 1));
        rm0 = fmaxf(rm0, __shfl_xor_sync(0xffffffffu, rm0, 2));
        rm1 = fmaxf(rm1, __shfl_xor_sync(0xffffffffu, rm1, 1));
        rm1 = fmaxf(rm1, __shfl_xor_sync(0xffffffffu, rm1, 2));

        float nm0 = fmaxf(mreg[0], rm0), nm1 = fmaxf(mreg[1], rm1);
        float a0 = ex2(mreg[0] - nm0), a1 = ex2(mreg[1] - nm1);
        mreg[0] = nm0; mreg[1] = nm1;

        // P = 2^(s-nm) in fp16x2 (half the MUFU ops)
        uint32_t p16[8][2];
#pragma unroll
        for (int nt = 0; nt < 8; nt++) {
            p16[nt][0] = h2ex2(pack_f16x2(s[nt][0] - nm0, s[nt][1] - nm0));
            p16[nt][1] = h2ex2(pack_f16x2(s[nt][2] - nm1, s[nt][3] - nm1));
        }

#pragma unroll
        for (int nt = 0; nt < 8; nt++) {
            o[nt][0] *= a0; o[nt][1] *= a0;
            o[nt][2] *= a1; o[nt][3] *= a1;
        }

        // ---- O += P V; row-sum l via ones-MMA ----
        float lacc[4] = {0.f, 0.f, 0.f, 0.f};
#pragma unroll
        for (int ks = 0; ks < 4; ks++) {
            const uint32_t vko = (uint32_t)ks * 2048u;
            uint32_t ph[4];
            ph[0] = p16[2 * ks][0];
            ph[1] = p16[2 * ks][1];
            ph[2] = p16[2 * ks + 1][0];
            ph[3] = p16[2 * ks + 1][1];

            mma_f16(lacc, ph, ONES_H2, ONES_H2);   // row sums of P

            uint32_t vh[4][4];
#pragma unroll
            for (int p2 = 0; p2 < 4; p2++)
                ldm_x4_t(vh[p2], kvb + 8192 + v_off[p2] + vko);
#pragma unroll
            for (int nt = 0; nt < 8; nt++) {
                int p2 = nt >> 1, q = nt & 1;
                mma_f16(o[nt], ph, vh[p2][2 * q], vh[p2][2 * q + 1]);
            }
        }
        lreg[0] = lreg[0] * a0 + lacc[0];
        lreg[1] = lreg[1] * a1 + lacc[2];
    }

    // Epilogue: normalize, write ctx fp16 [B*S, D]
    float inv0 = 1.f / lreg[0], inv1 = 1.f / lreg[1];
#pragma unroll
    for (int nt = 0; nt < 8; nt++) {
        int col = h * HDv + 8 * nt + 2 * t4;
        size_t r0 = ((size_t)b * Sv + gq0) * Dv + col;
        size_t r1 = ((size_t)b * Sv + gq1) * Dv + col;
        *(uint32_t*)(g_ch + r0) = pack_f16x2(o[nt][0] * inv0, o[nt][1] * inv0);
        *(uint32_t*)(g_ch + r1) = pack_f16x2(o[nt][2] * inv1, o[nt][3] * inv1);
    }
}

// ---------------------------------------------------------------------------
extern "C" void kernel_launch(void* const* d_in, const int* in_sizes, int n_in,
                              void* d_out, int out_size)
{
    const float* X  = (const float*)d_in[0];
    const float* Wq = (const float*)d_in[1];
    const float* Wk = (const float*)d_in[2];
    const float* Wv = (const float*)d_in[3];
    const float* Wo = (const float*)d_in[4];
    const float* bo = (const float*)d_in[5];
    float* out = (float*)d_out;

    cudaFuncSetAttribute(gemm_tc,
                         cudaFuncAttributeMaxDynamicSharedMemorySize, GEMM_SMEM);
    cudaFuncSetAttribute(attn_tc,
                         cudaFuncAttributeMaxDynamicSharedMemorySize, ATT_SMEM);

    const int nX4 = Mv * Dv / 4;
    const int nW4 = Dv * Dv / 4;

    cvt_x_kernel<<<nX4 / 256, 256>>>((const float4*)X);
    cvt_w_kernel<<<dim3(nW4 / 256, 4), 256>>>(
        (const float4*)Wq, (const float4*)Wk, (const float4*)Wv, (const float4*)Wo);

    gemm_tc<<<dim3(Dv / 128, Mv / 128, 3), 256, GEMM_SMEM>>>(0, nullptr, nullptr);

    attn_tc<<<dim3(Sv / 64, Hv, Bv), 128, ATT_SMEM>>>();

    gemm_tc<<<dim3(Dv / 128, Mv / 128, 1), 256, GEMM_SMEM>>>(1, out, bo);
}